// round 5
// baseline (speedup 1.0000x reference)
#include <cuda_runtime.h>
#include <math.h>

#define BATCH 8
#define SEQ   2048
#define DIM   1024
#define MSZ   (BATCH*SEQ)
typedef unsigned int u32;

#define NXD ((size_t)MSZ*DIM)       // 16M elems
#define NWD ((size_t)DIM*DIM)
#define NPP ((size_t)BATCH*SEQ*SEQ) // 33.5M elems

// tf32-exact fp32 hi/lo planes (allocation-free rule: __device__ globals)
__device__ float g_xqh[NXD], g_xql[NXD];
__device__ float g_xkh[NXD], g_xkl[NXD];
__device__ float g_xvh[NXD], g_xvl[NXD];
__device__ float g_wqh[NWD], g_wql[NWD];
__device__ float g_wkh[NWD], g_wkl[NWD];
__device__ float g_wvh[NWD], g_wvl[NWD];
__device__ float g_qh [NXD], g_ql [NXD];
__device__ float g_kh [NXD], g_kl [NXD];
__device__ float g_vth[NXD], g_vtl[NXD];   // v^T: [b][e][s]
__device__ float g_pph[NPP], g_ppl[NPP];

// ---------------- helpers ----------------
__device__ __forceinline__ float t32(float x) {
    u32 u; asm("cvt.rna.tf32.f32 %0, %1;" : "=r"(u) : "f"(x));
    return __uint_as_float(u);
}
__device__ __forceinline__ void mma8(float* c, const float* a, const float* b) {
    asm volatile(
        "mma.sync.aligned.m16n8k8.row.col.f32.tf32.tf32.f32 "
        "{%0,%1,%2,%3}, {%4,%5,%6,%7}, {%8,%9}, {%0,%1,%2,%3};"
        : "+f"(c[0]), "+f"(c[1]), "+f"(c[2]), "+f"(c[3])
        : "r"(__float_as_uint(a[0])), "r"(__float_as_uint(a[1])),
          "r"(__float_as_uint(a[2])), "r"(__float_as_uint(a[3])),
          "r"(__float_as_uint(b[0])), "r"(__float_as_uint(b[1])));
}
__device__ __forceinline__ u32 smem_u32(const void* p) {
    u32 a;
    asm("{ .reg .u64 t; cvta.to.shared.u64 t, %1; cvt.u32.u64 %0, t; }" : "=r"(a) : "l"(p));
    return a;
}
__device__ __forceinline__ void cp16(u32 s, const void* g) {
    asm volatile("cp.async.cg.shared.global [%0], [%1], 16;" :: "r"(s), "l"(g));
}
#define CP_COMMIT() asm volatile("cp.async.commit_group;" ::: "memory")
#define CP_WAIT0()  asm volatile("cp.async.wait_group 0;" ::: "memory")

// ---------------- split: fp32 -> tf32 hi/lo planes ----------------
__global__ __launch_bounds__(256) void split_k(const float* __restrict__ x,
    float* __restrict__ h, float* __restrict__ l, size_t n)
{
    size_t i = ((size_t)blockIdx.x * blockDim.x + threadIdx.x) * 4;
    const size_t st = (size_t)gridDim.x * blockDim.x * 4;
    for (; i < n; i += st) {
        float4 v = *(const float4*)(x + i);
        float4 hh, ll;
        hh.x = t32(v.x); ll.x = t32(v.x - hh.x);
        hh.y = t32(v.y); ll.y = t32(v.y - hh.y);
        hh.z = t32(v.z); ll.z = t32(v.z - hh.z);
        hh.w = t32(v.w); ll.w = t32(v.w - hh.w);
        *(float4*)(h + i) = hh;
        *(float4*)(l + i) = ll;
    }
}

// ---------------------------------------------------------------------------
// C[m,n] = scale * sum_k A[m,k]*B[n,k] (+ bias)  NT gemm, operands pre-split.
// Tiles 128x128x32, 8 warps (2m x 4n), warp tile 64x32, mma m16n8k8 tf32.
// Inner loop: pure LDS + HMMA. cp.async double-buffered tile fill.
// ---------------------------------------------------------------------------
#define LDT 36
#define TILE_F (128*LDT)
#define SMEM_BYTES (2*4*TILE_F*4)   // 2 bufs x (Ah,Al,Bh,Bl) = 147456 B

__global__ __launch_bounds__(256, 1) void gemm_tf32s(
    const float* __restrict__ Ah, const float* __restrict__ Al,
    const float* __restrict__ Bh, const float* __restrict__ Bl,
    const float* __restrict__ bias, int biasRow,
    float* __restrict__ C, float* __restrict__ Ch, float* __restrict__ Cl,
    int K, float scale, size_t sA, size_t sB, size_t sC, int ldc)
{
    extern __shared__ float sm[];
    const u32 sbase = smem_u32(sm);
    const int tid = threadIdx.x;
    const int wid = tid >> 5, lane = tid & 31;
    const int g = lane >> 2, tig = lane & 3;
    const int wm = (wid >> 2) * 64, wn = (wid & 3) * 32;
    const int z = blockIdx.z;

    const size_t aoff = z * sA + (size_t)(blockIdx.y * 128) * K;
    const size_t boff = z * sB + (size_t)(blockIdx.x * 128) * K;
    const float* gt[4] = { Ah + aoff, Al + aoff, Bh + boff, Bl + boff };

    const int lr = tid >> 3;            // 0..31 (+32,+64,+96)
    const int lc4 = (tid & 7) * 4;      // 0..28

    float acc[4][4][4];
#pragma unroll
    for (int mi = 0; mi < 4; mi++)
#pragma unroll
        for (int ni = 0; ni < 4; ni++)
#pragma unroll
            for (int r = 0; r < 4; r++) acc[mi][ni][r] = 0.0f;

    const int nch = K / 32;

    // issue tile loads for chunk c into buffer buf
    auto issue = [&](int c, int buf) {
        const int k0 = c * 32;
#pragma unroll
        for (int t = 0; t < 4; t++) {
            const float* gb = gt[t];
            const u32 s0 = sbase + (u32)((buf * 4 + t) * TILE_F) * 4;
#pragma unroll
            for (int i = 0; i < 4; i++) {
                const int row = lr + i * 32;
                cp16(s0 + (u32)(row * LDT + lc4) * 4,
                     gb + (size_t)row * K + k0 + lc4);
            }
        }
        CP_COMMIT();
    };

    issue(0, 0);

    for (int c = 0; c < nch; c++) {
        const int p = c & 1;
        CP_WAIT0();
        __syncthreads();
        if (c + 1 < nch) issue(c + 1, p ^ 1);

        const float* Ash = sm + (p * 4 + 0) * TILE_F;
        const float* Asl = sm + (p * 4 + 1) * TILE_F;
        const float* Bsh = sm + (p * 4 + 2) * TILE_F;
        const float* Bsl = sm + (p * 4 + 3) * TILE_F;

#pragma unroll
        for (int ks = 0; ks < 4; ks++) {
            const int kc = ks * 8 + tig;
            float ah[4][4], al[4][4], bh[4][2], bl[4][2];
#pragma unroll
            for (int mi = 0; mi < 4; mi++) {
                const int r0 = (wm + mi * 16 + g) * LDT;
                ah[mi][0] = Ash[r0 + kc];
                ah[mi][1] = Ash[r0 + 8 * LDT + kc];
                ah[mi][2] = Ash[r0 + kc + 4];
                ah[mi][3] = Ash[r0 + 8 * LDT + kc + 4];
                al[mi][0] = Asl[r0 + kc];
                al[mi][1] = Asl[r0 + 8 * LDT + kc];
                al[mi][2] = Asl[r0 + kc + 4];
                al[mi][3] = Asl[r0 + 8 * LDT + kc + 4];
            }
#pragma unroll
            for (int ni = 0; ni < 4; ni++) {
                const int rn = (wn + ni * 8 + g) * LDT;
                bh[ni][0] = Bsh[rn + kc];
                bh[ni][1] = Bsh[rn + kc + 4];
                bl[ni][0] = Bsl[rn + kc];
                bl[ni][1] = Bsl[rn + kc + 4];
            }
#pragma unroll
            for (int mi = 0; mi < 4; mi++)
#pragma unroll
                for (int ni = 0; ni < 4; ni++) mma8(acc[mi][ni], ah[mi], bh[ni]);
#pragma unroll
            for (int mi = 0; mi < 4; mi++)
#pragma unroll
                for (int ni = 0; ni < 4; ni++) mma8(acc[mi][ni], ah[mi], bl[ni]);
#pragma unroll
            for (int mi = 0; mi < 4; mi++)
#pragma unroll
                for (int ni = 0; ni < 4; ni++) mma8(acc[mi][ni], al[mi], bh[ni]);
        }
        __syncthreads();
    }

    // ---------------- epilogue ----------------
#pragma unroll
    for (int mi = 0; mi < 4; mi++) {
        const int row0 = blockIdx.y * 128 + wm + mi * 16 + g;
        const float br0 = (bias && biasRow) ? bias[row0] : 0.0f;
        const float br1 = (bias && biasRow) ? bias[row0 + 8] : 0.0f;
#pragma unroll
        for (int ni = 0; ni < 4; ni++) {
            const int col0 = blockIdx.x * 128 + wn + ni * 8 + tig * 2;
            float2 v0, v1;
            v0.x = acc[mi][ni][0] * scale; v0.y = acc[mi][ni][1] * scale;
            v1.x = acc[mi][ni][2] * scale; v1.y = acc[mi][ni][3] * scale;
            if (bias) {
                if (biasRow) { v0.x += br0; v0.y += br0; v1.x += br1; v1.y += br1; }
                else {
                    const float b0 = bias[col0], b1 = bias[col0 + 1];
                    v0.x += b0; v0.y += b1; v1.x += b0; v1.y += b1;
                }
            }
            const size_t o0 = z * sC + (size_t)row0 * ldc + col0;
            const size_t o1 = z * sC + (size_t)(row0 + 8) * ldc + col0;
            if (C) {
                *(float2*)(C + o0) = v0;
                *(float2*)(C + o1) = v1;
            }
            if (Ch) {
                float2 h0, h1, l0, l1;
                h0.x = t32(v0.x); l0.x = t32(v0.x - h0.x);
                h0.y = t32(v0.y); l0.y = t32(v0.y - h0.y);
                h1.x = t32(v1.x); l1.x = t32(v1.x - h1.x);
                h1.y = t32(v1.y); l1.y = t32(v1.y - h1.y);
                *(float2*)(Ch + o0) = h0; *(float2*)(Ch + o1) = h1;
                *(float2*)(Cl + o0) = l0; *(float2*)(Cl + o1) = l1;
            }
        }
    }
}

// ---------------------------------------------------------------------------
// In-place row softmax; also emits tf32 hi/lo planes of the result.
// ---------------------------------------------------------------------------
__global__ __launch_bounds__(256) void softmax_k(float* __restrict__ P,
    float* __restrict__ ph, float* __restrict__ pl)
{
    const size_t base = (size_t)blockIdx.x * SEQ;
    float* p = P + base;
    const int tid = threadIdx.x, lane = tid & 31, wid = tid >> 5;
    float4 a = ((const float4*)p)[tid * 2 + 0];
    float4 b = ((const float4*)p)[tid * 2 + 1];
    float x[8] = {a.x, a.y, a.z, a.w, b.x, b.y, b.z, b.w};
    __shared__ float red[8];

    float m = -INFINITY;
#pragma unroll
    for (int i = 0; i < 8; i++) m = fmaxf(m, x[i]);
#pragma unroll
    for (int o = 16; o > 0; o >>= 1) m = fmaxf(m, __shfl_xor_sync(0xffffffffu, m, o));
    if (lane == 0) red[wid] = m;
    __syncthreads();
    float mr = -INFINITY;
#pragma unroll
    for (int i = 0; i < 8; i++) mr = fmaxf(mr, red[i]);
    __syncthreads();

    float s = 0.0f;
#pragma unroll
    for (int i = 0; i < 8; i++) { x[i] = expf(x[i] - mr); s += x[i]; }
#pragma unroll
    for (int o = 16; o > 0; o >>= 1) s += __shfl_xor_sync(0xffffffffu, s, o);
    if (lane == 0) red[wid] = s;
    __syncthreads();
    float tot = 0.0f;
#pragma unroll
    for (int i = 0; i < 8; i++) tot += red[i];
    const float inv = 1.0f / tot;

    float4 o0, o1, h0, h1, l0, l1;
    o0.x = x[0] * inv; o0.y = x[1] * inv; o0.z = x[2] * inv; o0.w = x[3] * inv;
    o1.x = x[4] * inv; o1.y = x[5] * inv; o1.z = x[6] * inv; o1.w = x[7] * inv;
    ((float4*)p)[tid * 2 + 0] = o0;
    ((float4*)p)[tid * 2 + 1] = o1;
    h0.x = t32(o0.x); l0.x = t32(o0.x - h0.x);
    h0.y = t32(o0.y); l0.y = t32(o0.y - h0.y);
    h0.z = t32(o0.z); l0.z = t32(o0.z - h0.z);
    h0.w = t32(o0.w); l0.w = t32(o0.w - h0.w);
    h1.x = t32(o1.x); l1.x = t32(o1.x - h1.x);
    h1.y = t32(o1.y); l1.y = t32(o1.y - h1.y);
    h1.z = t32(o1.z); l1.z = t32(o1.z - h1.z);
    h1.w = t32(o1.w); l1.w = t32(o1.w - h1.w);
    ((float4*)(ph + base))[tid * 2 + 0] = h0;
    ((float4*)(ph + base))[tid * 2 + 1] = h1;
    ((float4*)(pl + base))[tid * 2 + 0] = l0;
    ((float4*)(pl + base))[tid * 2 + 1] = l1;
}

// ---------------------------------------------------------------------------
extern "C" void kernel_launch(void* const* d_in, const int* in_sizes, int n_in,
                              void* d_out, int out_size)
{
    const float* query = (const float*)d_in[0];
    const float* key   = (const float*)d_in[1];
    const float* value = (const float*)d_in[2];
    const float* Wq = (const float*)d_in[3]; const float* bq = (const float*)d_in[4];
    const float* Wk = (const float*)d_in[5]; const float* bk = (const float*)d_in[6];
    const float* Wv = (const float*)d_in[7]; const float* bv = (const float*)d_in[8];

    float* out_attn = (float*)d_out;
    float* out_smax = (float*)d_out + (size_t)MSZ * DIM;

    float *xqh,*xql,*xkh,*xkl,*xvh,*xvl,*wqh,*wql,*wkh,*wkl,*wvh,*wvl;
    float *qh,*ql,*kh,*kl,*vth,*vtl,*pph,*ppl;
    cudaGetSymbolAddress((void**)&xqh, g_xqh); cudaGetSymbolAddress((void**)&xql, g_xql);
    cudaGetSymbolAddress((void**)&xkh, g_xkh); cudaGetSymbolAddress((void**)&xkl, g_xkl);
    cudaGetSymbolAddress((void**)&xvh, g_xvh); cudaGetSymbolAddress((void**)&xvl, g_xvl);
    cudaGetSymbolAddress((void**)&wqh, g_wqh); cudaGetSymbolAddress((void**)&wql, g_wql);
    cudaGetSymbolAddress((void**)&wkh, g_wkh); cudaGetSymbolAddress((void**)&wkl, g_wkl);
    cudaGetSymbolAddress((void**)&wvh, g_wvh); cudaGetSymbolAddress((void**)&wvl, g_wvl);
    cudaGetSymbolAddress((void**)&qh,  g_qh);  cudaGetSymbolAddress((void**)&ql,  g_ql);
    cudaGetSymbolAddress((void**)&kh,  g_kh);  cudaGetSymbolAddress((void**)&kl,  g_kl);
    cudaGetSymbolAddress((void**)&vth, g_vth); cudaGetSymbolAddress((void**)&vtl, g_vtl);
    cudaGetSymbolAddress((void**)&pph, g_pph); cudaGetSymbolAddress((void**)&ppl, g_ppl);

    cudaFuncSetAttribute(gemm_tf32s, cudaFuncAttributeMaxDynamicSharedMemorySize, SMEM_BYTES);

    // 0) split inputs
    split_k<<<4096, 256>>>(query, xqh, xql, NXD);
    split_k<<<4096, 256>>>(key,   xkh, xkl, NXD);
    split_k<<<4096, 256>>>(value, xvh, xvl, NXD);
    split_k<<<512, 256>>>(Wq, wqh, wql, NWD);
    split_k<<<512, 256>>>(Wk, wkh, wkl, NWD);
    split_k<<<512, 256>>>(Wv, wvh, wvl, NWD);

    // 1) q/k projections -> hi/lo planes only
    {
        dim3 grid(DIM / 128, MSZ / 128, 1);
        gemm_tf32s<<<grid, 256, SMEM_BYTES>>>(xqh, xql, wqh, wql, bq, 0,
            nullptr, qh, ql, DIM, 1.0f, 0, 0, 0, DIM);
        gemm_tf32s<<<grid, 256, SMEM_BYTES>>>(xkh, xkl, wkh, wkl, bk, 0,
            nullptr, kh, kl, DIM, 1.0f, 0, 0, 0, DIM);
    }
    // 2) vT[b,e,s] = Wv[e,:] . value[b,s,:] + bv[e]
    {
        dim3 grid(SEQ / 128, DIM / 128, BATCH);
        gemm_tf32s<<<grid, 256, SMEM_BYTES>>>(wvh, wvl, xvh, xvl, bv, 1,
            nullptr, vth, vtl, DIM, 1.0f, 0, (size_t)SEQ * DIM, (size_t)DIM * SEQ, SEQ);
    }
    // 3) scores = 10 * q @ k^T -> fp32 (softmax output region)
    {
        dim3 grid(SEQ / 128, SEQ / 128, BATCH);
        gemm_tf32s<<<grid, 256, SMEM_BYTES>>>(qh, ql, kh, kl, nullptr, 0,
            out_smax, nullptr, nullptr, DIM, 10.0f,
            (size_t)SEQ * DIM, (size_t)SEQ * DIM, (size_t)SEQ * SEQ, SEQ);
    }
    // 4) softmax in place + P planes
    softmax_k<<<MSZ, 256>>>(out_smax, pph, ppl);
    // 5) out = P @ vT^T
    {
        dim3 grid(DIM / 128, SEQ / 128, BATCH);
        gemm_tf32s<<<grid, 256, SMEM_BYTES>>>(pph, ppl, vth, vtl, nullptr, 0,
            out_attn, nullptr, nullptr, SEQ, 1.0f,
            (size_t)SEQ * SEQ, (size_t)DIM * SEQ, (size_t)SEQ * DIM, DIM);
    }
}